// round 2
// baseline (speedup 1.0000x reference)
#include <cuda_runtime.h>

// ---------------------------------------------------------------------------
// CustomLSTM: B=2048, T=256, I=5, H=50, O=1
//
// R2 design: 512 blocks x 200 threads, NB=4 batches/block, 3 blocks/SM.
// f32x2 packs the K dimension (h_k, h_{k+1}) * (w_k, w_{k+1}) with one
// horizontal add per gate, halving weight register cost (w stays unpacked).
// Each thread owns one gate row; weights in registers; h/gates exchanged via
// tiny static shared (~4.5KB). x is prefetched one step ahead into a
// double-buffered 128B shared tile (no bulk staging). c-state in registers.
// ---------------------------------------------------------------------------

typedef unsigned long long ull;

constexpr int T  = 256;
constexpr int I  = 5;
constexpr int H  = 50;
constexpr int G  = 4 * H;    // 200
constexpr int NB = 4;        // batches per block
constexpr int NTH = 200;     // one thread per gate row
constexpr int NBLK = 2048 / NB; // 512
constexpr int HPAD = 52;     // h row stride in floats (208B, 16B-multiple)

__device__ __forceinline__ ull fma2(ull a, ull b, ull c) {
    ull d;
    asm("fma.rn.f32x2 %0, %1, %2, %3;" : "=l"(d) : "l"(a), "l"(b), "l"(c));
    return d;
}
__device__ __forceinline__ ull pack2(float x, float y) {
    ull r;
    asm("mov.b64 %0, {%1, %2};" : "=l"(r) : "f"(x), "f"(y));
    return r;
}
__device__ __forceinline__ float2 unpack2(ull v) {
    float2 r;
    asm("mov.b64 {%0, %1}, %2;" : "=f"(r.x), "=f"(r.y) : "l"(v));
    return r;
}
__device__ __forceinline__ float sigf(float x) {
    return __fdividef(1.0f, 1.0f + __expf(-x));
}
__device__ __forceinline__ float tanh_fast(float x) {
    float a = fabsf(x);
    float e = __expf(-2.0f * a);
    float t = __fdividef(1.0f - e, 1.0f + e);
    return copysignf(t, x);
}

__global__ void __launch_bounds__(NTH, 3) lstm_fused_kernel(
    const float* __restrict__ x,
    const float* __restrict__ Wxf, const float* __restrict__ bxf,
    const float* __restrict__ Wxi, const float* __restrict__ bxi,
    const float* __restrict__ Wxc, const float* __restrict__ bxc,
    const float* __restrict__ Wxo, const float* __restrict__ bxo,
    const float* __restrict__ Whf, const float* __restrict__ bhf,
    const float* __restrict__ Whi, const float* __restrict__ bhi,
    const float* __restrict__ Whc, const float* __restrict__ bhc,
    const float* __restrict__ Who, const float* __restrict__ bho,
    const float* __restrict__ bf,  const float* __restrict__ bi,
    const float* __restrict__ bc,  const float* __restrict__ bo,
    const float* __restrict__ Wfc, const float* __restrict__ bfc,
    float* __restrict__ out)
{
    __shared__ __align__(16) float gbf[NB * G];       // gate pre-activations
    __shared__ __align__(16) float hsf[NB * HPAD];    // h state, padded rows
    __shared__ __align__(16) ull   xbuf[2][NB * 4];   // x double buffer [b][4 ull]

    const int tid = threadIdx.x;
    const int b0  = blockIdx.x * NB;

    // ---- init shared: zero h (and padding) and xbuf (pad slots must be 0.0)
    for (int idx = tid; idx < NB * HPAD; idx += NTH) hsf[idx] = 0.0f;
    for (int idx = tid; idx < 2 * NB * 4; idx += NTH) xbuf[0][idx] = 0ull;

    // ---- this thread's gate row weights -> registers, k-packed f32x2
    const int g  = tid;          // 0..199
    const int q  = g / H;        // 0=f 1=i 2=c 3=o
    const int jj = g - q * H;
    const float* whp;
    const float* wxp;
    float btot;
    if (q == 0)      { whp = Whf + jj * H; wxp = Wxf + jj * I; btot = bxf[jj] + bhf[jj] + bf[jj]; }
    else if (q == 1) { whp = Whi + jj * H; wxp = Wxi + jj * I; btot = bxi[jj] + bhi[jj] + bi[jj]; }
    else if (q == 2) { whp = Whc + jj * H; wxp = Wxc + jj * I; btot = bxc[jj] + bhc[jj] + bc[jj]; }
    else             { whp = Who + jj * H; wxp = Wxo + jj * I; btot = bxo[jj] + bho[jj] + bo[jj]; }

    ull w2[H / 2];                     // (w_k, w_{k+1}) pairs: 25 ull = 50 regs
#pragma unroll
    for (int k = 0; k < H / 2; k++) w2[k] = pack2(whp[2 * k], whp[2 * k + 1]);
    ull wx2[3];
    wx2[0] = pack2(wxp[0], wxp[1]);
    wx2[1] = pack2(wxp[2], wxp[3]);
    wx2[2] = pack2(wxp[4], 0.0f);
    const ull bias_e = pack2(btot, 0.0f);

    // ---- stage x(t=0) into xbuf[0]
    if (tid < NB * I) {
        int pb = tid / I, pi = tid - pb * I;
        ((float*)xbuf[0])[pb * 8 + pi] = x[(size_t)(b0 + pb) * (T * I) + pi];
    }

    // ---- phase-B fixed mapping (one task per thread) + persistent c
    const int ub = tid / H;            // batch 0..3
    const int uj = tid - ub * H;       // unit 0..49
    float creg = 0.0f;

    __syncthreads();

    // =============================== time loop ==============================
    for (int t = 0; t < T; t++) {
        // prefetch x(t+1) into registers (hidden under phase A)
        float pf = 0.0f;
        const bool dofetch = (tid < NB * I) && (t + 1 < T);
        const int pb = tid / I, pi = tid - pb * I;
        if (dofetch) pf = x[(size_t)(b0 + pb) * (T * I) + (t + 1) * I + pi];

        const ull* xc = xbuf[t & 1];

        // ---- phase A: this thread's gate for all 4 batches
#pragma unroll
        for (int b = 0; b < NB; b++) {
            ull ae = bias_e;
            ull ao = 0ull;
            const float* hp = hsf + b * HPAD;
#pragma unroll
            for (int kk = 0; kk < 12; kk++) {
                ulonglong2 hv = *(const ulonglong2*)(hp + kk * 4);  // h[4k..4k+3] broadcast
                ae = fma2(hv.x, w2[2 * kk],     ae);
                ao = fma2(hv.y, w2[2 * kk + 1], ao);
            }
            {
                ull ht = *(const ull*)(hp + 48);                    // h[48..49]
                ae = fma2(ht, w2[24], ae);
            }
            {
                ulonglong2 xv = *(const ulonglong2*)(xc + b * 4);   // x[0..3]
                ull xv2 = xc[b * 4 + 2];                            // (x4, 0)
                ae = fma2(xv.x, wx2[0], ae);
                ao = fma2(xv.y, wx2[1], ao);
                ae = fma2(xv2,  wx2[2], ae);
            }
            float2 e = unpack2(ae), o = unpack2(ao);
            gbf[b * G + g] = (e.x + e.y) + (o.x + o.y);
        }
        __syncthreads();

        // park prefetched x into the other buffer (read two barriers from now)
        if (dofetch) ((float*)xbuf[(t + 1) & 1])[pb * 8 + pi] = pf;

        // ---- phase B: gate nonlinearity + state update (1 task/thread)
        {
            float gf = gbf[ub * G + uj];
            float gi = gbf[ub * G + H + uj];
            float gc = gbf[ub * G + 2 * H + uj];
            float go = gbf[ub * G + 3 * H + uj];
            creg = sigf(gf) * creg + sigf(gi) * tanh_fast(gc);
            hsf[ub * HPAD + uj] = sigf(go) * tanh_fast(creg);
        }
        __syncthreads();
    }

    // ---- final projection: out[b] = h_T[b] . Wfc + bfc   (O = 1)
    if (tid < NB) {
        const float* hp = hsf + tid * HPAD;
        float s = bfc[0];
#pragma unroll
        for (int k = 0; k < H; k++) s += hp[k] * Wfc[k];
        out[b0 + tid] = s;
    }
}

extern "C" void kernel_launch(void* const* d_in, const int* in_sizes, int n_in,
                              void* d_out, int out_size)
{
    (void)in_sizes; (void)n_in; (void)out_size;
    const float* x   = (const float*)d_in[0];
    const float* Wxf = (const float*)d_in[1];
    const float* bxf = (const float*)d_in[2];
    const float* Wxi = (const float*)d_in[3];
    const float* bxi = (const float*)d_in[4];
    const float* Wxc = (const float*)d_in[5];
    const float* bxc = (const float*)d_in[6];
    const float* Wxo = (const float*)d_in[7];
    const float* bxo = (const float*)d_in[8];
    const float* Whf = (const float*)d_in[9];
    const float* bhf = (const float*)d_in[10];
    const float* Whi = (const float*)d_in[11];
    const float* bhi = (const float*)d_in[12];
    const float* Whc = (const float*)d_in[13];
    const float* bhc = (const float*)d_in[14];
    const float* Who = (const float*)d_in[15];
    const float* bho = (const float*)d_in[16];
    const float* bf  = (const float*)d_in[17];
    const float* bi  = (const float*)d_in[18];
    const float* bc  = (const float*)d_in[19];
    const float* bo  = (const float*)d_in[20];
    const float* Wfc = (const float*)d_in[21];
    const float* bfc = (const float*)d_in[22];
    float* out = (float*)d_out;

    lstm_fused_kernel<<<NBLK, NTH>>>(
        x,
        Wxf, bxf, Wxi, bxi, Wxc, bxc, Wxo, bxo,
        Whf, bhf, Whi, bhi, Whc, bhc, Who, bho,
        bf, bi, bc, bo,
        Wfc, bfc,
        out);
}